// round 5
// baseline (speedup 1.0000x reference)
#include <cuda_runtime.h>
#include <cstdint>

// ============================================================
// spikes = ((X @ ternarize(S)^T) >= 1)
// X[8192,4096] f32 in [0,1), S[4096,4096] f32, Out[8192,4096] f32.
// Exact integer path: xq = rn(x*2^24) (clamped to 2^24-1) split
// into 3 u8 limbs; W ternary s8. GEMM via ldmatrix +
// mma.sync.m16n8k32.u8.s8.s32 (baseline PTX), K_eff = 3*4096.
// Limbs combined in-block: SMEM partial, Horner p = p*256 + acc.
// Final threshold is integer: sum >= 2^24  <=>  current >= 1.0.
// Stage fill via cp.async.bulk from pre-tiled pre-swizzled
// scratch (round-4 proven pipeline), 2 stages x 48KB + 128KB
// partial = 224KB SMEM.
// ============================================================

#define M_TOT 8192
#define N_TOT 4096
#define K_SRC 4096
#define BM 128
#define BN 256
#define NLIMB 3
#define KCH 128                      // int8 K elems per chunk = 128B row
#define CH_PER_LIMB (K_SRC / KCH)    // 32
#define NCHUNKS (NLIMB * CH_PER_LIMB)  // 96
#define A_STAGE 16384                // 128 rows x 128B
#define B_STAGE 32768                // 256 rows x 128B
#define STAGE_BYTES (A_STAGE + B_STAGE)      // 48KB
#define PART_OFF (2 * STAGE_BYTES)           // 98304
#define PART_BYTES (256 * 128 * 4)           // 128KB
#define SMEM_TOTAL (PART_OFF + PART_BYTES)   // 229376

// scratch: A [64 m-tiles][3 limbs][32 chunks][16KB], B [16 n-tiles][32 chunks][32KB]
__device__ __align__(128) unsigned char g_A8[64ull * NLIMB * CH_PER_LIMB * A_STAGE]; // 96MB
__device__ __align__(128) unsigned char g_B8[16ull * CH_PER_LIMB * B_STAGE];         // 16MB

__device__ __forceinline__ uint32_t smem_u32(const void* p) {
    uint32_t a;
    asm("{ .reg .u64 t; cvta.to.shared.u64 t, %1; cvt.u32.u64 %0, t; }" : "=r"(a) : "l"(p));
    return a;
}
__device__ __forceinline__ uint32_t sw128(uint32_t off) {
    return off ^ ((off >> 3) & 0x70);
}

#define MBAR_INIT(addr, cnt) \
    asm volatile("mbarrier.init.shared.b64 [%0], %1;" :: "r"(addr), "r"(cnt) : "memory")
#define MBAR_ARRIVE(addr) \
    asm volatile("mbarrier.arrive.shared.b64 _, [%0];" :: "r"(addr) : "memory")
#define MBAR_EXPECT_TX(addr, bytes) \
    asm volatile("mbarrier.arrive.expect_tx.shared.b64 _, [%0], %1;" \
                 :: "r"(addr), "r"(bytes) : "memory")
#define MBAR_WAIT(addr, parity) do { \
    uint32_t _m = (addr); uint32_t _p = (parity); uint32_t _d; \
    asm volatile("{\n\t.reg .pred p;\n\t" \
        "mbarrier.try_wait.parity.acquire.cta.shared::cta.b64 p, [%1], %2;\n\t" \
        "selp.b32 %0, 1, 0, p;\n\t}" : "=r"(_d) : "r"(_m), "r"(_p) : "memory"); \
    if (!_d) { \
        asm volatile("{\n\t.reg .pred P1;\n\tWL_%=:\n\t" \
            "mbarrier.try_wait.parity.acquire.cta.shared::cta.b64 P1, [%0], %1, 0x989680;\n\t" \
            "@P1 bra.uni WD_%=;\n\tbra.uni WL_%=;\n\tWD_%=:\n\t}" \
            :: "r"(_m), "r"(_p) : "memory"); \
    } } while (0)
#define CP_BULK(dst, src, bytes, mbar) \
    asm volatile("cp.async.bulk.shared::cluster.global.mbarrier::complete_tx::bytes " \
                 "[%0], [%1], %2, [%3];" \
                 :: "r"(dst), "l"(src), "r"(bytes), "r"(mbar) : "memory")
#define FENCE_ASYNC_SHARED() asm volatile("fence.proxy.async.shared::cta;" ::: "memory")

#define LDSM4(r0, r1, r2, r3, addr) \
    asm volatile("ldmatrix.sync.aligned.m8n8.x4.shared.b16 {%0,%1,%2,%3}, [%4];" \
                 : "=r"(r0), "=r"(r1), "=r"(r2), "=r"(r3) : "r"(addr))
#define MMAS8(c, a, b0, b1) \
    asm volatile("mma.sync.aligned.m16n8k32.row.col.s32.u8.s8.s32 " \
                 "{%0,%1,%2,%3}, {%4,%5,%6,%7}, {%8,%9}, {%0,%1,%2,%3};" \
                 : "+r"((c)[0]), "+r"((c)[1]), "+r"((c)[2]), "+r"((c)[3]) \
                 : "r"((a)[0]), "r"((a)[1]), "r"((a)[2]), "r"((a)[3]), \
                   "r"(b0), "r"(b1))

// ---------------- convert kernels ----------------
// A: xq = min(rn(x*2^24), 2^24-1); limbs u8: l0=hi, l1=mid, l2=lo.
__global__ __launch_bounds__(256)
void conv_a8(const float* __restrict__ X) {
    const int t = blockIdx.x;        // m128 tile 0..63
    const int c = blockIdx.y;        // chunk 0..31
    const int tid = threadIdx.x;
    const int r = tid >> 1, h = tid & 1;

    const float4* src = reinterpret_cast<const float4*>(
        X + (size_t)(t * 128 + r) * K_SRC + c * KCH + h * 64);
    unsigned char* base = g_A8 + ((size_t)t * (NLIMB * CH_PER_LIMB) + c) * A_STAGE;

#pragma unroll
    for (int j = 0; j < 4; j++) {
        uint32_t w0[4], w1[4], w2[4];
#pragma unroll
        for (int q = 0; q < 4; q++) {
            float4 f = src[j * 4 + q];
            int v0 = min(__float2int_rn(f.x * 16777216.0f), 16777215);
            int v1 = min(__float2int_rn(f.y * 16777216.0f), 16777215);
            int v2 = min(__float2int_rn(f.z * 16777216.0f), 16777215);
            int v3 = min(__float2int_rn(f.w * 16777216.0f), 16777215);
            w0[q] = ((uint32_t)(v0 >> 16) & 255u) | (((uint32_t)(v1 >> 16) & 255u) << 8) |
                    (((uint32_t)(v2 >> 16) & 255u) << 16) | (((uint32_t)(v3 >> 16) & 255u) << 24);
            w1[q] = ((uint32_t)(v0 >> 8) & 255u) | (((uint32_t)(v1 >> 8) & 255u) << 8) |
                    (((uint32_t)(v2 >> 8) & 255u) << 16) | (((uint32_t)(v3 >> 8) & 255u) << 24);
            w2[q] = ((uint32_t)v0 & 255u) | (((uint32_t)v1 & 255u) << 8) |
                    (((uint32_t)v2 & 255u) << 16) | (((uint32_t)v3 & 255u) << 24);
        }
        uint32_t sw = sw128((uint32_t)r * 128 + h * 64 + j * 16);
        *reinterpret_cast<uint4*>(base + sw) =
            make_uint4(w0[0], w0[1], w0[2], w0[3]);
        *reinterpret_cast<uint4*>(base + (size_t)CH_PER_LIMB * A_STAGE + sw) =
            make_uint4(w1[0], w1[1], w1[2], w1[3]);
        *reinterpret_cast<uint4*>(base + (size_t)2 * CH_PER_LIMB * A_STAGE + sw) =
            make_uint4(w2[0], w2[1], w2[2], w2[3]);
    }
}

__global__ __launch_bounds__(256)
void conv_w8(const float* __restrict__ S) {
    const int nt = blockIdx.x;       // n256 tile 0..15
    const int c = blockIdx.y;        // chunk 0..31
    const int r = threadIdx.x;       // row 0..255

    const float4* src = reinterpret_cast<const float4*>(
        S + (size_t)(nt * 256 + r) * K_SRC + c * KCH);
    unsigned char* dst = g_B8 + ((size_t)nt * CH_PER_LIMB + c) * B_STAGE;

#pragma unroll
    for (int j = 0; j < 8; j++) {
        uint32_t w[4];
#pragma unroll
        for (int q = 0; q < 4; q++) {
            float4 f = src[j * 4 + q];
            uint32_t b0 = (f.x > 1.0f) ? 1u : ((f.x < -1.0f) ? 0xFFu : 0u);
            uint32_t b1 = (f.y > 1.0f) ? 1u : ((f.y < -1.0f) ? 0xFFu : 0u);
            uint32_t b2 = (f.z > 1.0f) ? 1u : ((f.z < -1.0f) ? 0xFFu : 0u);
            uint32_t b3 = (f.w > 1.0f) ? 1u : ((f.w < -1.0f) ? 0xFFu : 0u);
            w[q] = b0 | (b1 << 8) | (b2 << 16) | (b3 << 24);
        }
        uint32_t sw = sw128((uint32_t)r * 128 + j * 16);
        *reinterpret_cast<uint4*>(dst + sw) = make_uint4(w[0], w[1], w[2], w[3]);
    }
}

// ---------------- GEMM ----------------
__global__ __launch_bounds__(256, 1)
void gemm8(float* __restrict__ Out) {
    extern __shared__ __align__(128) unsigned char smem[];
    __shared__ __align__(8) uint64_t s_mbar[4];   // [0..1]=full, [2..3]=empty

    const int tid = threadIdx.x;
    const int lane = tid & 31;
    const int wid = tid >> 5;
    const int wm = wid & 1;
    const int wn = wid >> 1;
    const int m0 = blockIdx.y * BM;
    const int n0 = blockIdx.x * BN;

    const uint32_t usmem = smem_u32(smem);
    uint32_t mb_full[2], mb_empty[2];
#pragma unroll
    for (int s = 0; s < 2; s++) {
        mb_full[s]  = smem_u32(&s_mbar[s]);
        mb_empty[s] = smem_u32(&s_mbar[s + 2]);
    }
    int* part = reinterpret_cast<int*>(smem + PART_OFF);

    const unsigned char* aSrc = g_A8 + (size_t)blockIdx.y * (NLIMB * CH_PER_LIMB) * A_STAGE;
    const unsigned char* bSrc = g_B8 + (size_t)blockIdx.x * CH_PER_LIMB * B_STAGE;

    if (tid == 0) {
#pragma unroll
        for (int s = 0; s < 2; s++) {
            MBAR_INIT(mb_full[s], 1);
            MBAR_INIT(mb_empty[s], 8);
        }
        FENCE_ASYNC_SHARED();
    }
    __syncthreads();

    // prologue: fill both stages (chunks 0,1)
    if (tid == 0) {
#pragma unroll
        for (int p = 0; p < 2; p++) {
            uint32_t dA = usmem + p * STAGE_BYTES;
            MBAR_EXPECT_TX(mb_full[p], (uint32_t)STAGE_BYTES);
            CP_BULK(dA,           aSrc + (size_t)p * A_STAGE, A_STAGE, mb_full[p]);
            CP_BULK(dA + A_STAGE, bSrc + (size_t)p * B_STAGE, B_STAGE, mb_full[p]);
        }
    }

    uint32_t rowoffA[4], rowoffB[4];
#pragma unroll
    for (int mt = 0; mt < 4; mt++)
        rowoffA[mt] = (uint32_t)(wm * 64 + mt * 16 + (lane & 15)) * 128;
#pragma unroll
    for (int nt = 0; nt < 4; nt++)
        rowoffB[nt] = (uint32_t)(wn * 64 + nt * 16 + ((lane >> 4) * 8 + (lane & 7))) * 128;
    const uint32_t xorv = (uint32_t)(lane & 7) * 16;
    const uint32_t colA_half = (uint32_t)(lane >> 4);
    const uint32_t colB_half = (uint32_t)((lane >> 3) & 1);

    int acc[4][8][4];
#pragma unroll
    for (int mt = 0; mt < 4; mt++)
#pragma unroll
        for (int nt = 0; nt < 8; nt++)
#pragma unroll
            for (int e = 0; e < 4; e++) acc[mt][nt][e] = 0;

    for (int cg = 0; cg < NCHUNKS; cg++) {
        const int st = cg & 1;
        const int ph = (cg >> 1) & 1;
        MBAR_WAIT(mb_full[st], ph);

        const uint32_t uA = usmem + st * STAGE_BYTES;
        const uint32_t uB = uA + A_STAGE;

#pragma unroll
        for (int ks = 0; ks < 4; ks++) {
            uint32_t a[4][4], b[4][4];
            const uint32_t cA = ((uint32_t)(ks * 2) + colA_half) * 16;
            const uint32_t cB = ((uint32_t)(ks * 2) + colB_half) * 16;
#pragma unroll
            for (int mt = 0; mt < 4; mt++)
                LDSM4(a[mt][0], a[mt][1], a[mt][2], a[mt][3],
                      uA + rowoffA[mt] + (cA ^ xorv));
#pragma unroll
            for (int nt = 0; nt < 4; nt++)
                LDSM4(b[nt][0], b[nt][1], b[nt][2], b[nt][3],
                      uB + rowoffB[nt] + (cB ^ xorv));
#pragma unroll
            for (int mt = 0; mt < 4; mt++)
#pragma unroll
                for (int nt = 0; nt < 4; nt++) {
                    MMAS8(acc[mt][2 * nt],     a[mt], b[nt][0], b[nt][1]);
                    MMAS8(acc[mt][2 * nt + 1], a[mt], b[nt][2], b[nt][3]);
                }
        }

        if (lane == 0) MBAR_ARRIVE(mb_empty[st]);

        if (tid == 0 && cg + 2 < NCHUNKS) {
            MBAR_WAIT(mb_empty[st], ph);
            const int cn = cg + 2;
            uint32_t dA = usmem + st * STAGE_BYTES;
            MBAR_EXPECT_TX(mb_full[st], (uint32_t)STAGE_BYTES);
            CP_BULK(dA,           aSrc + (size_t)cn * A_STAGE,                  A_STAGE, mb_full[st]);
            CP_BULK(dA + A_STAGE, bSrc + (size_t)(cn % CH_PER_LIMB) * B_STAGE, B_STAGE, mb_full[st]);
        }

        // limb boundaries: Horner fold into SMEM partial (per-thread private slots)
        if (cg == CH_PER_LIMB - 1) {
#pragma unroll
            for (int mt = 0; mt < 4; mt++)
#pragma unroll
                for (int nt = 0; nt < 8; nt++)
#pragma unroll
                    for (int e = 0; e < 4; e++) {
                        int j = (mt * 8 + nt) * 4 + e;
                        part[j * 256 + tid] = acc[mt][nt][e];
                        acc[mt][nt][e] = 0;
                    }
        } else if (cg == 2 * CH_PER_LIMB - 1) {
#pragma unroll
            for (int mt = 0; mt < 4; mt++)
#pragma unroll
                for (int nt = 0; nt < 8; nt++)
#pragma unroll
                    for (int e = 0; e < 4; e++) {
                        int j = (mt * 8 + nt) * 4 + e;
                        part[j * 256 + tid] = part[j * 256 + tid] * 256 + acc[mt][nt][e];
                        acc[mt][nt][e] = 0;
                    }
        }
    }

    // epilogue: integer threshold  sum >= 2^24  <=>  current >= 1.0
#pragma unroll
    for (int mt = 0; mt < 4; mt++) {
        const int row = m0 + wm * 64 + mt * 16 + (lane >> 2);
#pragma unroll
        for (int nt = 0; nt < 8; nt++) {
            const int col = n0 + wn * 64 + nt * 8 + (lane & 3) * 2;
            float v[4];
#pragma unroll
            for (int e = 0; e < 4; e++) {
                int j = (mt * 8 + nt) * 4 + e;
                long long s = (long long)part[j * 256 + tid] * 256 + acc[mt][nt][e];
                v[e] = (s >= 16777216LL) ? 1.0f : 0.0f;
            }
            *reinterpret_cast<float2*>(Out + (size_t)row * N_TOT + col) =
                make_float2(v[0], v[1]);
            *reinterpret_cast<float2*>(Out + (size_t)(row + 8) * N_TOT + col) =
                make_float2(v[2], v[3]);
        }
    }
}

// ---------------- host ----------------
extern "C" void kernel_launch(void* const* d_in, const int* in_sizes, int n_in,
                              void* d_out, int out_size) {
    const float* X = (const float*)d_in[0];   // [8192, 4096]
    const float* S = (const float*)d_in[1];   // [4096, 4096]
    float* Out = (float*)d_out;

    cudaFuncSetAttribute(gemm8, cudaFuncAttributeMaxDynamicSharedMemorySize, SMEM_TOTAL);

    conv_a8<<<dim3(64, 32), 256>>>(X);
    conv_w8<<<dim3(16, 32), 256>>>(S);
    gemm8<<<dim3(N_TOT / BN, M_TOT / BM), 256, SMEM_TOTAL>>>(Out);
}

// round 6
// speedup vs baseline: 5.9616x; 5.9616x over previous
#include <cuda_runtime.h>
#include <cuda_fp16.h>
#include <cstdint>

// ============================================================
// spikes = ((X @ ternarize(S)^T) >= 1)
// Threshold-margin split:
//  - hi-GEMM: fp16 hi limb only (K=4096) via ldmatrix+mma.sync
//    m16n8k16 + cp.async.bulk pipeline (round-4 proven core).
//  - outputs with |hi_sum - 1| <= 0.15 (~0.35%) appended to a
//    list; exact fixup adds lo limb (s16, scale 2^27) x w (s8)
//    via dp2a, then re-thresholds.
//  Hoeffding: P(|lo-sum| > 0.13) = exp(-41) -> margin safe.
// ============================================================

#define M_TOT 8192
#define N_TOT 4096
#define K_SRC 4096
#define BM 128
#define BN 256
#define NCHUNKS 64                  // K64 fp16 per chunk (128B rows)
#define STAGES 4
#define A_STAGE 16384               // 128 rows x 128B
#define B_STAGE 32768               // 256 rows x 128B
#define STAGE_BYTES (A_STAGE + B_STAGE)       // 48KB
#define SMEM_TOTAL (STAGES * STAGE_BYTES)     // 192KB
#define LIST_CAP (1u << 21)         // 2M entries (expect ~118K)

// scratch
__device__ __align__(128) unsigned char g_Ahi[64ull * NCHUNKS * A_STAGE];  // 64MB swizzled hi
__device__ __align__(128) unsigned char g_B[16ull * NCHUNKS * B_STAGE];    // 32MB swizzled w f16
__device__ __align__(128) short g_lo16[(size_t)M_TOT * K_SRC];             // 64MB plain lo s16
__device__ __align__(128) signed char g_w8[(size_t)N_TOT * K_SRC];         // 16MB plain w s8
__device__ unsigned int g_cnt;
__device__ unsigned int g_mn[LIST_CAP];
__device__ float g_hs[LIST_CAP];

__device__ __forceinline__ uint32_t smem_u32(const void* p) {
    uint32_t a;
    asm("{ .reg .u64 t; cvta.to.shared.u64 t, %1; cvt.u32.u64 %0, t; }" : "=r"(a) : "l"(p));
    return a;
}
__device__ __forceinline__ uint32_t sw128(uint32_t off) {
    return off ^ ((off >> 3) & 0x70);
}

#define MBAR_INIT(addr, cnt) \
    asm volatile("mbarrier.init.shared.b64 [%0], %1;" :: "r"(addr), "r"(cnt) : "memory")
#define MBAR_ARRIVE(addr) \
    asm volatile("mbarrier.arrive.shared.b64 _, [%0];" :: "r"(addr) : "memory")
#define MBAR_EXPECT_TX(addr, bytes) \
    asm volatile("mbarrier.arrive.expect_tx.shared.b64 _, [%0], %1;" \
                 :: "r"(addr), "r"(bytes) : "memory")
#define MBAR_WAIT(addr, parity) do { \
    uint32_t _m = (addr); uint32_t _p = (parity); uint32_t _d; \
    asm volatile("{\n\t.reg .pred p;\n\t" \
        "mbarrier.try_wait.parity.acquire.cta.shared::cta.b64 p, [%1], %2;\n\t" \
        "selp.b32 %0, 1, 0, p;\n\t}" : "=r"(_d) : "r"(_m), "r"(_p) : "memory"); \
    if (!_d) { \
        asm volatile("{\n\t.reg .pred P1;\n\tWL_%=:\n\t" \
            "mbarrier.try_wait.parity.acquire.cta.shared::cta.b64 P1, [%0], %1, 0x989680;\n\t" \
            "@P1 bra.uni WD_%=;\n\tbra.uni WL_%=;\n\tWD_%=:\n\t}" \
            :: "r"(_m), "r"(_p) : "memory"); \
    } } while (0)
#define CP_BULK(dst, src, bytes, mbar) \
    asm volatile("cp.async.bulk.shared::cluster.global.mbarrier::complete_tx::bytes " \
                 "[%0], [%1], %2, [%3];" \
                 :: "r"(dst), "l"(src), "r"(bytes), "r"(mbar) : "memory")
#define FENCE_ASYNC_SHARED() asm volatile("fence.proxy.async.shared::cta;" ::: "memory")

#define LDSM4(r0, r1, r2, r3, addr) \
    asm volatile("ldmatrix.sync.aligned.m8n8.x4.shared.b16 {%0,%1,%2,%3}, [%4];" \
                 : "=r"(r0), "=r"(r1), "=r"(r2), "=r"(r3) : "r"(addr))
#define MMA16816(c, a, b0, b1) \
    asm volatile("mma.sync.aligned.m16n8k16.row.col.f32.f16.f16.f32 " \
                 "{%0,%1,%2,%3}, {%4,%5,%6,%7}, {%8,%9}, {%0,%1,%2,%3};" \
                 : "+f"((c)[0]), "+f"((c)[1]), "+f"((c)[2]), "+f"((c)[3]) \
                 : "r"((a)[0]), "r"((a)[1]), "r"((a)[2]), "r"((a)[3]), \
                   "r"(b0), "r"(b1))

// ---------------- convert kernels ----------------
// hi = rn16(x) -> swizzled scratch; lo = rn(( x - hi ) * 2^27) s16 plain.
__global__ __launch_bounds__(256)
void conv_a(const float* __restrict__ X) {
    const int t = blockIdx.x;        // m128 tile 0..63
    const int c = blockIdx.y;        // chunk 0..63 (K64)
    const int tid = threadIdx.x;
    const int r = tid >> 1, h = tid & 1;

    const float4* src = reinterpret_cast<const float4*>(
        X + (size_t)(t * 128 + r) * K_SRC + c * 64 + h * 32);
    unsigned char* dhi = g_Ahi + ((size_t)t * NCHUNKS + c) * A_STAGE;
    short* dlo = g_lo16 + (size_t)(t * 128 + r) * K_SRC + c * 64 + h * 32;

#pragma unroll
    for (int j = 0; j < 4; j++) {
        float4 f0 = src[j * 2], f1 = src[j * 2 + 1];
        float xs[8] = {f0.x, f0.y, f0.z, f0.w, f1.x, f1.y, f1.z, f1.w};
        __half2 hh[4];
        uint32_t lw[4];
#pragma unroll
        for (int e = 0; e < 4; e++) {
            __half a = __float2half_rn(xs[2 * e]);
            __half b = __float2half_rn(xs[2 * e + 1]);
            hh[e] = __halves2half2(a, b);
            int la = __float2int_rn((xs[2 * e]     - __half2float(a)) * 134217728.0f);
            int lb = __float2int_rn((xs[2 * e + 1] - __half2float(b)) * 134217728.0f);
            la = max(min(la, 32767), -32768);
            lb = max(min(lb, 32767), -32768);
            lw[e] = ((uint32_t)la & 0xFFFFu) | ((uint32_t)lb << 16);
        }
        uint32_t sw = sw128((uint32_t)r * 128 + h * 64 + j * 16);
        *reinterpret_cast<uint4*>(dhi + sw) = *reinterpret_cast<uint4*>(hh);
        *reinterpret_cast<uint4*>(dlo + j * 8) = make_uint4(lw[0], lw[1], lw[2], lw[3]);
    }
}

__global__ __launch_bounds__(256)
void conv_w(const float* __restrict__ S) {
    const int nt = blockIdx.x;       // n256 tile 0..15
    const int c = blockIdx.y;        // chunk 0..63 (K64)
    const int r = threadIdx.x;       // row 0..255

    const float4* src = reinterpret_cast<const float4*>(
        S + (size_t)(nt * 256 + r) * K_SRC + c * 64);
    unsigned char* dst = g_B + ((size_t)nt * NCHUNKS + c) * B_STAGE;
    signed char* d8 = g_w8 + (size_t)(nt * 256 + r) * K_SRC + c * 64;

    uint32_t pk[16];
#pragma unroll
    for (int j = 0; j < 8; j++) {
        float4 f0 = src[j * 2], f1 = src[j * 2 + 1];
        float xs[8] = {f0.x, f0.y, f0.z, f0.w, f1.x, f1.y, f1.z, f1.w};
        __half2 ww[4];
        uint32_t b0 = 0, b1 = 0;
#pragma unroll
        for (int e = 0; e < 4; e++) {
            float wa = (xs[2 * e]     > 1.0f) ? 1.0f : ((xs[2 * e]     < -1.0f) ? -1.0f : 0.0f);
            float wb = (xs[2 * e + 1] > 1.0f) ? 1.0f : ((xs[2 * e + 1] < -1.0f) ? -1.0f : 0.0f);
            ww[e] = __halves2half2(__float2half_rn(wa), __float2half_rn(wb));
            uint32_t ba = (xs[2 * e]     > 1.0f) ? 1u : ((xs[2 * e]     < -1.0f) ? 0xFFu : 0u);
            uint32_t bb = (xs[2 * e + 1] > 1.0f) ? 1u : ((xs[2 * e + 1] < -1.0f) ? 0xFFu : 0u);
            if (e < 2) b0 |= (ba << (e * 16)) | (bb << (e * 16 + 8));
            else       b1 |= (ba << ((e - 2) * 16)) | (bb << ((e - 2) * 16 + 8));
        }
        uint32_t sw = sw128((uint32_t)r * 128 + j * 16);
        *reinterpret_cast<uint4*>(dst + sw) = *reinterpret_cast<uint4*>(ww);
        pk[j * 2] = b0; pk[j * 2 + 1] = b1;
    }
#pragma unroll
    for (int q = 0; q < 4; q++)
        *reinterpret_cast<uint4*>(d8 + q * 16) =
            make_uint4(pk[q * 4], pk[q * 4 + 1], pk[q * 4 + 2], pk[q * 4 + 3]);
}

__global__ void zero_cnt() { g_cnt = 0; }

// ---------------- hi GEMM ----------------
__global__ __launch_bounds__(256, 1)
void gemm_hi(float* __restrict__ Out) {
    extern __shared__ __align__(128) unsigned char smem[];
    __shared__ __align__(8) uint64_t s_mbar[8];

    const int tid = threadIdx.x;
    const int lane = tid & 31;
    const int wid = tid >> 5;
    const int wm = wid & 1;
    const int wn = wid >> 1;
    const int m0 = blockIdx.y * BM;
    const int n0 = blockIdx.x * BN;

    const uint32_t usmem = smem_u32(smem);
    uint32_t mb_full[STAGES], mb_empty[STAGES];
#pragma unroll
    for (int s = 0; s < STAGES; s++) {
        mb_full[s]  = smem_u32(&s_mbar[s]);
        mb_empty[s] = smem_u32(&s_mbar[s + 4]);
    }

    const unsigned char* aSrc = g_Ahi + (size_t)blockIdx.y * NCHUNKS * A_STAGE;
    const unsigned char* bSrc = g_B + (size_t)blockIdx.x * NCHUNKS * B_STAGE;

    if (tid == 0) {
#pragma unroll
        for (int s = 0; s < STAGES; s++) {
            MBAR_INIT(mb_full[s], 1);
            MBAR_INIT(mb_empty[s], 8);
        }
        FENCE_ASYNC_SHARED();
    }
    __syncthreads();

    if (tid == 0) {
#pragma unroll
        for (int p = 0; p < STAGES; p++) {
            uint32_t dA = usmem + p * STAGE_BYTES;
            MBAR_EXPECT_TX(mb_full[p], (uint32_t)STAGE_BYTES);
            CP_BULK(dA,           aSrc + (size_t)p * A_STAGE, A_STAGE, mb_full[p]);
            CP_BULK(dA + A_STAGE, bSrc + (size_t)p * B_STAGE, B_STAGE, mb_full[p]);
        }
    }

    uint32_t rowoffA[4], rowoffB[4];
#pragma unroll
    for (int mt = 0; mt < 4; mt++)
        rowoffA[mt] = (uint32_t)(wm * 64 + mt * 16 + (lane & 15)) * 128;
#pragma unroll
    for (int nt = 0; nt < 4; nt++)
        rowoffB[nt] = (uint32_t)(wn * 64 + nt * 16 + ((lane >> 4) * 8 + (lane & 7))) * 128;
    const uint32_t xorv = (uint32_t)(lane & 7) * 16;
    const uint32_t colA_half = (uint32_t)(lane >> 4);
    const uint32_t colB_half = (uint32_t)((lane >> 3) & 1);

    float acc[4][8][4];
#pragma unroll
    for (int mt = 0; mt < 4; mt++)
#pragma unroll
        for (int nt = 0; nt < 8; nt++)
#pragma unroll
            for (int e = 0; e < 4; e++) acc[mt][nt][e] = 0.0f;

    for (int c = 0; c < NCHUNKS; c++) {
        const int st = c & 3;
        const int ph = (c >> 2) & 1;
        MBAR_WAIT(mb_full[st], ph);

        const uint32_t uA = usmem + st * STAGE_BYTES;
        const uint32_t uB = uA + A_STAGE;

#pragma unroll
        for (int ks = 0; ks < 4; ks++) {
            uint32_t a[4][4], b[4][4];
            const uint32_t cA = ((uint32_t)(ks * 2) + colA_half) * 16;
            const uint32_t cB = ((uint32_t)(ks * 2) + colB_half) * 16;
#pragma unroll
            for (int mt = 0; mt < 4; mt++)
                LDSM4(a[mt][0], a[mt][1], a[mt][2], a[mt][3],
                      uA + rowoffA[mt] + (cA ^ xorv));
#pragma unroll
            for (int nt = 0; nt < 4; nt++)
                LDSM4(b[nt][0], b[nt][1], b[nt][2], b[nt][3],
                      uB + rowoffB[nt] + (cB ^ xorv));
#pragma unroll
            for (int mt = 0; mt < 4; mt++)
#pragma unroll
                for (int nt = 0; nt < 4; nt++) {
                    MMA16816(acc[mt][2 * nt],     a[mt], b[nt][0], b[nt][1]);
                    MMA16816(acc[mt][2 * nt + 1], a[mt], b[nt][2], b[nt][3]);
                }
        }

        if (lane == 0) MBAR_ARRIVE(mb_empty[st]);

        if (tid == 0 && c + STAGES < NCHUNKS) {
            MBAR_WAIT(mb_empty[st], ph);
            const int cn = c + STAGES;
            uint32_t dA = usmem + st * STAGE_BYTES;
            MBAR_EXPECT_TX(mb_full[st], (uint32_t)STAGE_BYTES);
            CP_BULK(dA,           aSrc + (size_t)cn * A_STAGE, A_STAGE, mb_full[st]);
            CP_BULK(dA + A_STAGE, bSrc + (size_t)cn * B_STAGE, B_STAGE, mb_full[st]);
        }
    }

    // epilogue: provisional threshold + uncertain-list append
#pragma unroll
    for (int mt = 0; mt < 4; mt++) {
        const int row = m0 + wm * 64 + mt * 16 + (lane >> 2);
#pragma unroll
        for (int nt = 0; nt < 8; nt++) {
            const int col = n0 + wn * 64 + nt * 8 + (lane & 3) * 2;
            const float s0 = acc[mt][nt][0], s1 = acc[mt][nt][1];
            const float s2 = acc[mt][nt][2], s3 = acc[mt][nt][3];
            *reinterpret_cast<float2*>(Out + (size_t)row * N_TOT + col) =
                make_float2((s0 >= 1.0f) ? 1.0f : 0.0f, (s1 >= 1.0f) ? 1.0f : 0.0f);
            *reinterpret_cast<float2*>(Out + (size_t)(row + 8) * N_TOT + col) =
                make_float2((s2 >= 1.0f) ? 1.0f : 0.0f, (s3 >= 1.0f) ? 1.0f : 0.0f);
            if (s0 > 0.85f && s0 < 1.15f) {
                unsigned int i = atomicAdd(&g_cnt, 1u);
                if (i < LIST_CAP) { g_mn[i] = ((unsigned)row << 12) | (unsigned)col; g_hs[i] = s0; }
            }
            if (s1 > 0.85f && s1 < 1.15f) {
                unsigned int i = atomicAdd(&g_cnt, 1u);
                if (i < LIST_CAP) { g_mn[i] = ((unsigned)row << 12) | (unsigned)(col + 1); g_hs[i] = s1; }
            }
            if (s2 > 0.85f && s2 < 1.15f) {
                unsigned int i = atomicAdd(&g_cnt, 1u);
                if (i < LIST_CAP) { g_mn[i] = ((unsigned)(row + 8) << 12) | (unsigned)col; g_hs[i] = s2; }
            }
            if (s3 > 0.85f && s3 < 1.15f) {
                unsigned int i = atomicAdd(&g_cnt, 1u);
                if (i < LIST_CAP) { g_mn[i] = ((unsigned)(row + 8) << 12) | (unsigned)(col + 1); g_hs[i] = s3; }
            }
        }
    }
}

// ---------------- fixup ----------------
__global__ __launch_bounds__(256)
void fixup(float* __restrict__ Out) {
    const int lane = threadIdx.x & 31;
    const int gw = blockIdx.x * (blockDim.x >> 5) + (threadIdx.x >> 5);
    const int nwarps = gridDim.x * (blockDim.x >> 5);
    const unsigned int cnt = min(g_cnt, LIST_CAP);

    for (unsigned int i = gw; i < cnt; i += nwarps) {
        const unsigned int mn = g_mn[i];
        const float hs = g_hs[i];
        const int m = mn >> 12, n = mn & 4095;

        const uint4* lp = reinterpret_cast<const uint4*>(g_lo16 + (size_t)m * K_SRC) + lane * 16;
        const uint4* wp = reinterpret_cast<const uint4*>(g_w8  + (size_t)n * K_SRC) + lane * 8;

        int s = 0;
#pragma unroll
        for (int q = 0; q < 8; q++) {
            uint4 wv = wp[q];
            uint4 l0 = lp[2 * q], l1 = lp[2 * q + 1];
            s = __dp2a_lo((int)l0.x, (int)wv.x, s);
            s = __dp2a_hi((int)l0.y, (int)wv.x, s);
            s = __dp2a_lo((int)l0.z, (int)wv.y, s);
            s = __dp2a_hi((int)l0.w, (int)wv.y, s);
            s = __dp2a_lo((int)l1.x, (int)wv.z, s);
            s = __dp2a_hi((int)l1.y, (int)wv.z, s);
            s = __dp2a_lo((int)l1.z, (int)wv.w, s);
            s = __dp2a_hi((int)l1.w, (int)wv.w, s);
        }
#pragma unroll
        for (int off = 16; off; off >>= 1)
            s += __shfl_xor_sync(0xFFFFFFFFu, s, off);

        if (lane == 0) {
            const float tot = hs + (float)s * 7.4505805969238281e-9f;   // 2^-27
            Out[(size_t)m * N_TOT + n] = (tot >= 1.0f) ? 1.0f : 0.0f;
        }
    }
}

// ---------------- host ----------------
extern "C" void kernel_launch(void* const* d_in, const int* in_sizes, int n_in,
                              void* d_out, int out_size) {
    const float* X = (const float*)d_in[0];   // [8192, 4096]
    const float* S = (const float*)d_in[1];   // [4096, 4096]
    float* Out = (float*)d_out;

    cudaFuncSetAttribute(gemm_hi, cudaFuncAttributeMaxDynamicSharedMemorySize, SMEM_TOTAL);

    conv_a<<<dim3(64, 64), 256>>>(X);
    conv_w<<<dim3(16, 64), 256>>>(S);
    zero_cnt<<<1, 1>>>();
    gemm_hi<<<dim3(N_TOT / BN, M_TOT / BM), 256, SMEM_TOTAL>>>(Out);
    fixup<<<1024, 256>>>(Out);
}

// round 7
// speedup vs baseline: 6.4304x; 1.0786x over previous
#include <cuda_runtime.h>
#include <cuda_fp16.h>
#include <cstdint>

// ============================================================
// spikes = ((X @ ternarize(S)^T) >= 1)
// Threshold-margin split (round-6 proven) + persistent-CTA GEMM:
//  - hi-GEMM: fp16 hi limb (K=4096), ldmatrix+mma.sync m16n8k16,
//    cp.async.bulk 4-stage ring. Grid=148 persistent CTAs; the
//    chunk stream is continuous across tiles so the pipeline
//    never drains at tile boundaries (kills wave-transition +
//    per-tile prologue idle).
//  - |hi_sum-1| <= 0.12 outputs (~0.28%) get exact fixup with
//    lo s16 (scale 2^27) x w s8 via dp2a.
// ============================================================

#define M_TOT 8192
#define N_TOT 4096
#define K_SRC 4096
#define BM 128
#define BN 256
#define NCHUNKS 64                  // K64 fp16 per chunk (128B rows)
#define STAGES 4
#define A_STAGE 16384               // 128 rows x 128B
#define B_STAGE 32768               // 256 rows x 128B
#define STAGE_BYTES (A_STAGE + B_STAGE)       // 48KB
#define SMEM_TOTAL (STAGES * STAGE_BYTES)     // 192KB
#define NSM 148
#define NTILES ((M_TOT / BM) * (N_TOT / BN))  // 1024
#define LIST_CAP (1u << 21)

// scratch
__device__ __align__(128) unsigned char g_Ahi[64ull * NCHUNKS * A_STAGE];  // 64MB swizzled hi
__device__ __align__(128) unsigned char g_B[16ull * NCHUNKS * B_STAGE];    // 32MB swizzled w f16
__device__ __align__(128) short g_lo16[(size_t)M_TOT * K_SRC];             // 64MB plain lo s16
__device__ __align__(128) signed char g_w8[(size_t)N_TOT * K_SRC];         // 16MB plain w s8
__device__ unsigned int g_cnt;
__device__ unsigned int g_mn[LIST_CAP];
__device__ float g_hs[LIST_CAP];

__device__ __forceinline__ uint32_t smem_u32(const void* p) {
    uint32_t a;
    asm("{ .reg .u64 t; cvta.to.shared.u64 t, %1; cvt.u32.u64 %0, t; }" : "=r"(a) : "l"(p));
    return a;
}
__device__ __forceinline__ uint32_t sw128(uint32_t off) {
    return off ^ ((off >> 3) & 0x70);
}

#define MBAR_INIT(addr, cnt) \
    asm volatile("mbarrier.init.shared.b64 [%0], %1;" :: "r"(addr), "r"(cnt) : "memory")
#define MBAR_ARRIVE(addr) \
    asm volatile("mbarrier.arrive.shared.b64 _, [%0];" :: "r"(addr) : "memory")
#define MBAR_EXPECT_TX(addr, bytes) \
    asm volatile("mbarrier.arrive.expect_tx.shared.b64 _, [%0], %1;" \
                 :: "r"(addr), "r"(bytes) : "memory")
#define MBAR_WAIT(addr, parity) do { \
    uint32_t _m = (addr); uint32_t _p = (parity); uint32_t _d; \
    asm volatile("{\n\t.reg .pred p;\n\t" \
        "mbarrier.try_wait.parity.acquire.cta.shared::cta.b64 p, [%1], %2;\n\t" \
        "selp.b32 %0, 1, 0, p;\n\t}" : "=r"(_d) : "r"(_m), "r"(_p) : "memory"); \
    if (!_d) { \
        asm volatile("{\n\t.reg .pred P1;\n\tWL_%=:\n\t" \
            "mbarrier.try_wait.parity.acquire.cta.shared::cta.b64 P1, [%0], %1, 0x989680;\n\t" \
            "@P1 bra.uni WD_%=;\n\tbra.uni WL_%=;\n\tWD_%=:\n\t}" \
            :: "r"(_m), "r"(_p) : "memory"); \
    } } while (0)
#define CP_BULK(dst, src, bytes, mbar) \
    asm volatile("cp.async.bulk.shared::cluster.global.mbarrier::complete_tx::bytes " \
                 "[%0], [%1], %2, [%3];" \
                 :: "r"(dst), "l"(src), "r"(bytes), "r"(mbar) : "memory")
#define FENCE_ASYNC_SHARED() asm volatile("fence.proxy.async.shared::cta;" ::: "memory")

#define LDSM4(r0, r1, r2, r3, addr) \
    asm volatile("ldmatrix.sync.aligned.m8n8.x4.shared.b16 {%0,%1,%2,%3}, [%4];" \
                 : "=r"(r0), "=r"(r1), "=r"(r2), "=r"(r3) : "r"(addr))
#define MMA16816(c, a, b0, b1) \
    asm volatile("mma.sync.aligned.m16n8k16.row.col.f32.f16.f16.f32 " \
                 "{%0,%1,%2,%3}, {%4,%5,%6,%7}, {%8,%9}, {%0,%1,%2,%3};" \
                 : "+f"((c)[0]), "+f"((c)[1]), "+f"((c)[2]), "+f"((c)[3]) \
                 : "r"((a)[0]), "r"((a)[1]), "r"((a)[2]), "r"((a)[3]), \
                   "r"(b0), "r"(b1))

// ---------------- merged convert kernel ----------------
// x < 64: A path (hi fp16 swizzled + lo s16 plain); x >= 64: W path.
__global__ __launch_bounds__(256)
void conv_all(const float* __restrict__ X, const float* __restrict__ S) {
    if (blockIdx.x == 0 && blockIdx.y == 0 && threadIdx.x == 0) g_cnt = 0;

    if (blockIdx.x < 64) {
        const int t = blockIdx.x;        // m128 tile
        const int c = blockIdx.y;        // chunk 0..63
        const int tid = threadIdx.x;
        const int r = tid >> 1, h = tid & 1;

        const float4* src = reinterpret_cast<const float4*>(
            X + (size_t)(t * 128 + r) * K_SRC + c * 64 + h * 32);
        unsigned char* dhi = g_Ahi + ((size_t)t * NCHUNKS + c) * A_STAGE;
        short* dlo = g_lo16 + (size_t)(t * 128 + r) * K_SRC + c * 64 + h * 32;

#pragma unroll
        for (int j = 0; j < 4; j++) {
            float4 f0 = src[j * 2], f1 = src[j * 2 + 1];
            float xs[8] = {f0.x, f0.y, f0.z, f0.w, f1.x, f1.y, f1.z, f1.w};
            __half2 hh[4];
            uint32_t lw[4];
#pragma unroll
            for (int e = 0; e < 4; e++) {
                __half a = __float2half_rn(xs[2 * e]);
                __half b = __float2half_rn(xs[2 * e + 1]);
                hh[e] = __halves2half2(a, b);
                int la = __float2int_rn((xs[2 * e]     - __half2float(a)) * 134217728.0f);
                int lb = __float2int_rn((xs[2 * e + 1] - __half2float(b)) * 134217728.0f);
                la = max(min(la, 32767), -32768);
                lb = max(min(lb, 32767), -32768);
                lw[e] = ((uint32_t)la & 0xFFFFu) | ((uint32_t)lb << 16);
            }
            uint32_t sw = sw128((uint32_t)r * 128 + h * 64 + j * 16);
            *reinterpret_cast<uint4*>(dhi + sw) = *reinterpret_cast<uint4*>(hh);
            *reinterpret_cast<uint4*>(dlo + j * 8) = make_uint4(lw[0], lw[1], lw[2], lw[3]);
        }
    } else if (blockIdx.x < 80) {
        const int nt = blockIdx.x - 64;  // n256 tile
        const int c = blockIdx.y;        // chunk 0..63
        const int r = threadIdx.x;       // row 0..255

        const float4* src = reinterpret_cast<const float4*>(
            S + (size_t)(nt * 256 + r) * K_SRC + c * 64);
        unsigned char* dst = g_B + ((size_t)nt * NCHUNKS + c) * B_STAGE;
        signed char* d8 = g_w8 + (size_t)(nt * 256 + r) * K_SRC + c * 64;

        uint32_t pk[16];
#pragma unroll
        for (int j = 0; j < 8; j++) {
            float4 f0 = src[j * 2], f1 = src[j * 2 + 1];
            float xs[8] = {f0.x, f0.y, f0.z, f0.w, f1.x, f1.y, f1.z, f1.w};
            __half2 ww[4];
            uint32_t b0 = 0, b1 = 0;
#pragma unroll
            for (int e = 0; e < 4; e++) {
                float wa = (xs[2 * e]     > 1.0f) ? 1.0f : ((xs[2 * e]     < -1.0f) ? -1.0f : 0.0f);
                float wb = (xs[2 * e + 1] > 1.0f) ? 1.0f : ((xs[2 * e + 1] < -1.0f) ? -1.0f : 0.0f);
                ww[e] = __halves2half2(__float2half_rn(wa), __float2half_rn(wb));
                uint32_t ba = (xs[2 * e]     > 1.0f) ? 1u : ((xs[2 * e]     < -1.0f) ? 0xFFu : 0u);
                uint32_t bb = (xs[2 * e + 1] > 1.0f) ? 1u : ((xs[2 * e + 1] < -1.0f) ? 0xFFu : 0u);
                if (e < 2) b0 |= (ba << (e * 16)) | (bb << (e * 16 + 8));
                else       b1 |= (ba << ((e - 2) * 16)) | (bb << ((e - 2) * 16 + 8));
            }
            uint32_t sw = sw128((uint32_t)r * 128 + j * 16);
            *reinterpret_cast<uint4*>(dst + sw) = *reinterpret_cast<uint4*>(ww);
            pk[j * 2] = b0; pk[j * 2 + 1] = b1;
        }
#pragma unroll
        for (int q = 0; q < 4; q++)
            *reinterpret_cast<uint4*>(d8 + q * 16) =
                make_uint4(pk[q * 4], pk[q * 4 + 1], pk[q * 4 + 2], pk[q * 4 + 3]);
    }
}

// ---------------- persistent hi GEMM ----------------
__device__ __forceinline__ void fill_chunk(uint32_t usmem, uint32_t mbar, int bx, int L) {
    const int w = L >> 6, c = L & 63;
    const int t = bx + w * NSM;
    const int m = t >> 4, n = t & 15;
    const uint32_t dA = usmem + (L & 3) * STAGE_BYTES;
    MBAR_EXPECT_TX(mbar, (uint32_t)STAGE_BYTES);
    CP_BULK(dA,           g_Ahi + ((size_t)m * NCHUNKS + c) * A_STAGE, A_STAGE, mbar);
    CP_BULK(dA + A_STAGE, g_B  + ((size_t)n * NCHUNKS + c) * B_STAGE, B_STAGE, mbar);
}

__global__ __launch_bounds__(256, 1)
void gemm_hi(float* __restrict__ Out) {
    extern __shared__ __align__(128) unsigned char smem[];
    __shared__ __align__(8) uint64_t s_mbar[8];

    const int tid = threadIdx.x;
    const int lane = tid & 31;
    const int wid = tid >> 5;
    const int wm = wid & 1;
    const int wn = wid >> 1;
    const int bx = blockIdx.x;              // 0..147 persistent

    const int nT = (NTILES - bx + NSM - 1) / NSM;
    const int totL = nT * NCHUNKS;

    const uint32_t usmem = smem_u32(smem);
    uint32_t mb_full[STAGES], mb_empty[STAGES];
#pragma unroll
    for (int s = 0; s < STAGES; s++) {
        mb_full[s]  = smem_u32(&s_mbar[s]);
        mb_empty[s] = smem_u32(&s_mbar[s + 4]);
    }

    if (tid == 0) {
#pragma unroll
        for (int s = 0; s < STAGES; s++) {
            MBAR_INIT(mb_full[s], 1);
            MBAR_INIT(mb_empty[s], 8);
        }
        FENCE_ASYNC_SHARED();
    }
    __syncthreads();

    if (tid == 0) {
#pragma unroll
        for (int p = 0; p < STAGES; p++) fill_chunk(usmem, mb_full[p], bx, p);
    }

    uint32_t rowoffA[4], rowoffB[4];
#pragma unroll
    for (int mt = 0; mt < 4; mt++)
        rowoffA[mt] = (uint32_t)(wm * 64 + mt * 16 + (lane & 15)) * 128;
#pragma unroll
    for (int nt = 0; nt < 4; nt++)
        rowoffB[nt] = (uint32_t)(wn * 64 + nt * 16 + ((lane >> 4) * 8 + (lane & 7))) * 128;
    const uint32_t xorv = (uint32_t)(lane & 7) * 16;
    const uint32_t colA_half = (uint32_t)(lane >> 4);
    const uint32_t colB_half = (uint32_t)((lane >> 3) & 1);

    float acc[4][8][4];
#pragma unroll
    for (int mt = 0; mt < 4; mt++)
#pragma unroll
        for (int nt = 0; nt < 8; nt++)
#pragma unroll
            for (int e = 0; e < 4; e++) acc[mt][nt][e] = 0.0f;

    for (int L = 0; L < totL; L++) {
        const int st = L & 3;
        const int ph = (L >> 2) & 1;
        MBAR_WAIT(mb_full[st], ph);

        const uint32_t uA = usmem + st * STAGE_BYTES;
        const uint32_t uB = uA + A_STAGE;

#pragma unroll
        for (int ks = 0; ks < 4; ks++) {
            uint32_t a[4][4], b[4][4];
            const uint32_t cA = ((uint32_t)(ks * 2) + colA_half) * 16;
            const uint32_t cB = ((uint32_t)(ks * 2) + colB_half) * 16;
#pragma unroll
            for (int mt = 0; mt < 4; mt++)
                LDSM4(a[mt][0], a[mt][1], a[mt][2], a[mt][3],
                      uA + rowoffA[mt] + (cA ^ xorv));
#pragma unroll
            for (int nt = 0; nt < 4; nt++)
                LDSM4(b[nt][0], b[nt][1], b[nt][2], b[nt][3],
                      uB + rowoffB[nt] + (cB ^ xorv));
#pragma unroll
            for (int mt = 0; mt < 4; mt++)
#pragma unroll
                for (int nt = 0; nt < 4; nt++) {
                    MMA16816(acc[mt][2 * nt],     a[mt], b[nt][0], b[nt][1]);
                    MMA16816(acc[mt][2 * nt + 1], a[mt], b[nt][2], b[nt][3]);
                }
        }

        if (lane == 0) MBAR_ARRIVE(mb_empty[st]);

        if (tid == 0 && L + STAGES < totL) {
            MBAR_WAIT(mb_empty[st], ph);
            fill_chunk(usmem, mb_full[st], bx, L + STAGES);
        }

        if ((L & 63) == 63) {
            // tile epilogue (producer keeps filling next tile's stages meanwhile)
            const int t = bx + (L >> 6) * NSM;
            const int m0 = (t >> 4) * BM;
            const int n0 = (t & 15) * BN;
#pragma unroll
            for (int mt = 0; mt < 4; mt++) {
                const int row = m0 + wm * 64 + mt * 16 + (lane >> 2);
#pragma unroll
                for (int nt = 0; nt < 8; nt++) {
                    const int col = n0 + wn * 64 + nt * 8 + (lane & 3) * 2;
                    const float s0 = acc[mt][nt][0], s1 = acc[mt][nt][1];
                    const float s2 = acc[mt][nt][2], s3 = acc[mt][nt][3];
                    *reinterpret_cast<float2*>(Out + (size_t)row * N_TOT + col) =
                        make_float2((s0 >= 1.0f) ? 1.0f : 0.0f, (s1 >= 1.0f) ? 1.0f : 0.0f);
                    *reinterpret_cast<float2*>(Out + (size_t)(row + 8) * N_TOT + col) =
                        make_float2((s2 >= 1.0f) ? 1.0f : 0.0f, (s3 >= 1.0f) ? 1.0f : 0.0f);
                    if (s0 > 0.88f && s0 < 1.12f) {
                        unsigned int i = atomicAdd(&g_cnt, 1u);
                        if (i < LIST_CAP) { g_mn[i] = ((unsigned)row << 12) | (unsigned)col; g_hs[i] = s0; }
                    }
                    if (s1 > 0.88f && s1 < 1.12f) {
                        unsigned int i = atomicAdd(&g_cnt, 1u);
                        if (i < LIST_CAP) { g_mn[i] = ((unsigned)row << 12) | (unsigned)(col + 1); g_hs[i] = s1; }
                    }
                    if (s2 > 0.88f && s2 < 1.12f) {
                        unsigned int i = atomicAdd(&g_cnt, 1u);
                        if (i < LIST_CAP) { g_mn[i] = ((unsigned)(row + 8) << 12) | (unsigned)col; g_hs[i] = s2; }
                    }
                    if (s3 > 0.88f && s3 < 1.12f) {
                        unsigned int i = atomicAdd(&g_cnt, 1u);
                        if (i < LIST_CAP) { g_mn[i] = ((unsigned)(row + 8) << 12) | (unsigned)(col + 1); g_hs[i] = s3; }
                    }
#pragma unroll
                    for (int e = 0; e < 4; e++) acc[mt][nt][e] = 0.0f;
                }
            }
        }
    }
}

// ---------------- fixup ----------------
__global__ __launch_bounds__(256)
void fixup(float* __restrict__ Out) {
    const int lane = threadIdx.x & 31;
    const int gw = blockIdx.x * (blockDim.x >> 5) + (threadIdx.x >> 5);
    const int nwarps = gridDim.x * (blockDim.x >> 5);
    const unsigned int cnt = min(g_cnt, LIST_CAP);

    for (unsigned int i = gw; i < cnt; i += nwarps) {
        const unsigned int mn = g_mn[i];
        const float hs = g_hs[i];
        const int m = mn >> 12, n = mn & 4095;

        const uint4* lp = reinterpret_cast<const uint4*>(g_lo16 + (size_t)m * K_SRC) + lane * 16;
        const uint4* wp = reinterpret_cast<const uint4*>(g_w8  + (size_t)n * K_SRC) + lane * 8;

        int s = 0;
#pragma unroll
        for (int q = 0; q < 8; q++) {
            uint4 wv = wp[q];
            uint4 l0 = lp[2 * q], l1 = lp[2 * q + 1];
            s = __dp2a_lo((int)l0.x, (int)wv.x, s);
            s = __dp2a_hi((int)l0.y, (int)wv.x, s);
            s = __dp2a_lo((int)l0.z, (int)wv.y, s);
            s = __dp2a_hi((int)l0.w, (int)wv.y, s);
            s = __dp2a_lo((int)l1.x, (int)wv.z, s);
            s = __dp2a_hi((int)l1.y, (int)wv.z, s);
            s = __dp2a_lo((int)l1.z, (int)wv.w, s);
            s = __dp2a_hi((int)l1.w, (int)wv.w, s);
        }
#pragma unroll
        for (int off = 16; off; off >>= 1)
            s += __shfl_xor_sync(0xFFFFFFFFu, s, off);

        if (lane == 0) {
            const float tot = hs + (float)s * 7.4505805969238281e-9f;   // 2^-27
            Out[(size_t)m * N_TOT + n] = (tot >= 1.0f) ? 1.0f : 0.0f;
        }
    }
}

// ---------------- host ----------------
extern "C" void kernel_launch(void* const* d_in, const int* in_sizes, int n_in,
                              void* d_out, int out_size) {
    const float* X = (const float*)d_in[0];   // [8192, 4096]
    const float* S = (const float*)d_in[1];   // [4096, 4096]
    float* Out = (float*)d_out;

    cudaFuncSetAttribute(gemm_hi, cudaFuncAttributeMaxDynamicSharedMemorySize, SMEM_TOTAL);

    conv_all<<<dim3(80, 64), 256>>>(X, S);
    gemm_hi<<<NSM, 256, SMEM_TOTAL>>>(Out);
    fixup<<<1024, 256>>>(Out);
}

// round 8
// speedup vs baseline: 7.6762x; 1.1937x over previous
#include <cuda_runtime.h>
#include <cuda_fp16.h>
#include <cstdint>

// ============================================================
// spikes = ((X @ ternarize(S)^T) >= 1)
// Threshold-margin split + persistent-CTA hi-GEMM (round-7 core).
// This round: margin tightened 0.88-1.12 -> 0.95-1.05 (6 sigma of
// the lo-limb sum, sigma~8.2e-3) => fixup list ~2.4x smaller,
// fixup kernel ~260us -> ~110us.
// ============================================================

#define M_TOT 8192
#define N_TOT 4096
#define K_SRC 4096
#define BM 128
#define BN 256
#define NCHUNKS 64                  // K64 fp16 per chunk (128B rows)
#define STAGES 4
#define A_STAGE 16384               // 128 rows x 128B
#define B_STAGE 32768               // 256 rows x 128B
#define STAGE_BYTES (A_STAGE + B_STAGE)       // 48KB
#define SMEM_TOTAL (STAGES * STAGE_BYTES)     // 192KB
#define NSM 148
#define NTILES ((M_TOT / BM) * (N_TOT / BN))  // 1024
#define LIST_CAP (1u << 21)
#define MARG_LO 0.95f
#define MARG_HI 1.05f

// scratch
__device__ __align__(128) unsigned char g_Ahi[64ull * NCHUNKS * A_STAGE];  // 64MB swizzled hi
__device__ __align__(128) unsigned char g_B[16ull * NCHUNKS * B_STAGE];    // 32MB swizzled w f16
__device__ __align__(128) short g_lo16[(size_t)M_TOT * K_SRC];             // 64MB plain lo s16
__device__ __align__(128) signed char g_w8[(size_t)N_TOT * K_SRC];         // 16MB plain w s8
__device__ unsigned int g_cnt;
__device__ unsigned int g_mn[LIST_CAP];
__device__ float g_hs[LIST_CAP];

__device__ __forceinline__ uint32_t smem_u32(const void* p) {
    uint32_t a;
    asm("{ .reg .u64 t; cvta.to.shared.u64 t, %1; cvt.u32.u64 %0, t; }" : "=r"(a) : "l"(p));
    return a;
}
__device__ __forceinline__ uint32_t sw128(uint32_t off) {
    return off ^ ((off >> 3) & 0x70);
}

#define MBAR_INIT(addr, cnt) \
    asm volatile("mbarrier.init.shared.b64 [%0], %1;" :: "r"(addr), "r"(cnt) : "memory")
#define MBAR_ARRIVE(addr) \
    asm volatile("mbarrier.arrive.shared.b64 _, [%0];" :: "r"(addr) : "memory")
#define MBAR_EXPECT_TX(addr, bytes) \
    asm volatile("mbarrier.arrive.expect_tx.shared.b64 _, [%0], %1;" \
                 :: "r"(addr), "r"(bytes) : "memory")
#define MBAR_WAIT(addr, parity) do { \
    uint32_t _m = (addr); uint32_t _p = (parity); uint32_t _d; \
    asm volatile("{\n\t.reg .pred p;\n\t" \
        "mbarrier.try_wait.parity.acquire.cta.shared::cta.b64 p, [%1], %2;\n\t" \
        "selp.b32 %0, 1, 0, p;\n\t}" : "=r"(_d) : "r"(_m), "r"(_p) : "memory"); \
    if (!_d) { \
        asm volatile("{\n\t.reg .pred P1;\n\tWL_%=:\n\t" \
            "mbarrier.try_wait.parity.acquire.cta.shared::cta.b64 P1, [%0], %1, 0x989680;\n\t" \
            "@P1 bra.uni WD_%=;\n\tbra.uni WL_%=;\n\tWD_%=:\n\t}" \
            :: "r"(_m), "r"(_p) : "memory"); \
    } } while (0)
#define CP_BULK(dst, src, bytes, mbar) \
    asm volatile("cp.async.bulk.shared::cluster.global.mbarrier::complete_tx::bytes " \
                 "[%0], [%1], %2, [%3];" \
                 :: "r"(dst), "l"(src), "r"(bytes), "r"(mbar) : "memory")
#define FENCE_ASYNC_SHARED() asm volatile("fence.proxy.async.shared::cta;" ::: "memory")

#define LDSM4(r0, r1, r2, r3, addr) \
    asm volatile("ldmatrix.sync.aligned.m8n8.x4.shared.b16 {%0,%1,%2,%3}, [%4];" \
                 : "=r"(r0), "=r"(r1), "=r"(r2), "=r"(r3) : "r"(addr))
#define MMA16816(c, a, b0, b1) \
    asm volatile("mma.sync.aligned.m16n8k16.row.col.f32.f16.f16.f32 " \
                 "{%0,%1,%2,%3}, {%4,%5,%6,%7}, {%8,%9}, {%0,%1,%2,%3};" \
                 : "+f"((c)[0]), "+f"((c)[1]), "+f"((c)[2]), "+f"((c)[3]) \
                 : "r"((a)[0]), "r"((a)[1]), "r"((a)[2]), "r"((a)[3]), \
                   "r"(b0), "r"(b1))

// ---------------- merged convert kernel ----------------
__global__ __launch_bounds__(256)
void conv_all(const float* __restrict__ X, const float* __restrict__ S) {
    if (blockIdx.x == 0 && blockIdx.y == 0 && threadIdx.x == 0) g_cnt = 0;

    if (blockIdx.x < 64) {
        const int t = blockIdx.x;        // m128 tile
        const int c = blockIdx.y;        // chunk 0..63
        const int tid = threadIdx.x;
        const int r = tid >> 1, h = tid & 1;

        const float4* src = reinterpret_cast<const float4*>(
            X + (size_t)(t * 128 + r) * K_SRC + c * 64 + h * 32);
        unsigned char* dhi = g_Ahi + ((size_t)t * NCHUNKS + c) * A_STAGE;
        short* dlo = g_lo16 + (size_t)(t * 128 + r) * K_SRC + c * 64 + h * 32;

#pragma unroll
        for (int j = 0; j < 4; j++) {
            float4 f0 = src[j * 2], f1 = src[j * 2 + 1];
            float xs[8] = {f0.x, f0.y, f0.z, f0.w, f1.x, f1.y, f1.z, f1.w};
            __half2 hh[4];
            uint32_t lw[4];
#pragma unroll
            for (int e = 0; e < 4; e++) {
                __half a = __float2half_rn(xs[2 * e]);
                __half b = __float2half_rn(xs[2 * e + 1]);
                hh[e] = __halves2half2(a, b);
                int la = __float2int_rn((xs[2 * e]     - __half2float(a)) * 134217728.0f);
                int lb = __float2int_rn((xs[2 * e + 1] - __half2float(b)) * 134217728.0f);
                la = max(min(la, 32767), -32768);
                lb = max(min(lb, 32767), -32768);
                lw[e] = ((uint32_t)la & 0xFFFFu) | ((uint32_t)lb << 16);
            }
            uint32_t sw = sw128((uint32_t)r * 128 + h * 64 + j * 16);
            *reinterpret_cast<uint4*>(dhi + sw) = *reinterpret_cast<uint4*>(hh);
            *reinterpret_cast<uint4*>(dlo + j * 8) = make_uint4(lw[0], lw[1], lw[2], lw[3]);
        }
    } else if (blockIdx.x < 80) {
        const int nt = blockIdx.x - 64;  // n256 tile
        const int c = blockIdx.y;        // chunk 0..63
        const int r = threadIdx.x;       // row 0..255

        const float4* src = reinterpret_cast<const float4*>(
            S + (size_t)(nt * 256 + r) * K_SRC + c * 64);
        unsigned char* dst = g_B + ((size_t)nt * NCHUNKS + c) * B_STAGE;
        signed char* d8 = g_w8 + (size_t)(nt * 256 + r) * K_SRC + c * 64;

        uint32_t pk[16];
#pragma unroll
        for (int j = 0; j < 8; j++) {
            float4 f0 = src[j * 2], f1 = src[j * 2 + 1];
            float xs[8] = {f0.x, f0.y, f0.z, f0.w, f1.x, f1.y, f1.z, f1.w};
            __half2 ww[4];
            uint32_t b0 = 0, b1 = 0;
#pragma unroll
            for (int e = 0; e < 4; e++) {
                float wa = (xs[2 * e]     > 1.0f) ? 1.0f : ((xs[2 * e]     < -1.0f) ? -1.0f : 0.0f);
                float wb = (xs[2 * e + 1] > 1.0f) ? 1.0f : ((xs[2 * e + 1] < -1.0f) ? -1.0f : 0.0f);
                ww[e] = __halves2half2(__float2half_rn(wa), __float2half_rn(wb));
                uint32_t ba = (xs[2 * e]     > 1.0f) ? 1u : ((xs[2 * e]     < -1.0f) ? 0xFFu : 0u);
                uint32_t bb = (xs[2 * e + 1] > 1.0f) ? 1u : ((xs[2 * e + 1] < -1.0f) ? 0xFFu : 0u);
                if (e < 2) b0 |= (ba << (e * 16)) | (bb << (e * 16 + 8));
                else       b1 |= (ba << ((e - 2) * 16)) | (bb << ((e - 2) * 16 + 8));
            }
            uint32_t sw = sw128((uint32_t)r * 128 + j * 16);
            *reinterpret_cast<uint4*>(dst + sw) = *reinterpret_cast<uint4*>(ww);
            pk[j * 2] = b0; pk[j * 2 + 1] = b1;
        }
#pragma unroll
        for (int q = 0; q < 4; q++)
            *reinterpret_cast<uint4*>(d8 + q * 16) =
                make_uint4(pk[q * 4], pk[q * 4 + 1], pk[q * 4 + 2], pk[q * 4 + 3]);
    }
}

// ---------------- persistent hi GEMM ----------------
__device__ __forceinline__ void fill_chunk(uint32_t usmem, uint32_t mbar, int bx, int L) {
    const int w = L >> 6, c = L & 63;
    const int t = bx + w * NSM;
    const int m = t >> 4, n = t & 15;
    const uint32_t dA = usmem + (L & 3) * STAGE_BYTES;
    MBAR_EXPECT_TX(mbar, (uint32_t)STAGE_BYTES);
    CP_BULK(dA,           g_Ahi + ((size_t)m * NCHUNKS + c) * A_STAGE, A_STAGE, mbar);
    CP_BULK(dA + A_STAGE, g_B  + ((size_t)n * NCHUNKS + c) * B_STAGE, B_STAGE, mbar);
}

__global__ __launch_bounds__(256, 1)
void gemm_hi(float* __restrict__ Out) {
    extern __shared__ __align__(128) unsigned char smem[];
    __shared__ __align__(8) uint64_t s_mbar[8];

    const int tid = threadIdx.x;
    const int lane = tid & 31;
    const int wid = tid >> 5;
    const int wm = wid & 1;
    const int wn = wid >> 1;
    const int bx = blockIdx.x;              // 0..147 persistent

    const int nT = (NTILES - bx + NSM - 1) / NSM;
    const int totL = nT * NCHUNKS;

    const uint32_t usmem = smem_u32(smem);
    uint32_t mb_full[STAGES], mb_empty[STAGES];
#pragma unroll
    for (int s = 0; s < STAGES; s++) {
        mb_full[s]  = smem_u32(&s_mbar[s]);
        mb_empty[s] = smem_u32(&s_mbar[s + 4]);
    }

    if (tid == 0) {
#pragma unroll
        for (int s = 0; s < STAGES; s++) {
            MBAR_INIT(mb_full[s], 1);
            MBAR_INIT(mb_empty[s], 8);
        }
        FENCE_ASYNC_SHARED();
    }
    __syncthreads();

    if (tid == 0) {
#pragma unroll
        for (int p = 0; p < STAGES; p++) fill_chunk(usmem, mb_full[p], bx, p);
    }

    uint32_t rowoffA[4], rowoffB[4];
#pragma unroll
    for (int mt = 0; mt < 4; mt++)
        rowoffA[mt] = (uint32_t)(wm * 64 + mt * 16 + (lane & 15)) * 128;
#pragma unroll
    for (int nt = 0; nt < 4; nt++)
        rowoffB[nt] = (uint32_t)(wn * 64 + nt * 16 + ((lane >> 4) * 8 + (lane & 7))) * 128;
    const uint32_t xorv = (uint32_t)(lane & 7) * 16;
    const uint32_t colA_half = (uint32_t)(lane >> 4);
    const uint32_t colB_half = (uint32_t)((lane >> 3) & 1);

    float acc[4][8][4];
#pragma unroll
    for (int mt = 0; mt < 4; mt++)
#pragma unroll
        for (int nt = 0; nt < 8; nt++)
#pragma unroll
            for (int e = 0; e < 4; e++) acc[mt][nt][e] = 0.0f;

    for (int L = 0; L < totL; L++) {
        const int st = L & 3;
        const int ph = (L >> 2) & 1;
        MBAR_WAIT(mb_full[st], ph);

        const uint32_t uA = usmem + st * STAGE_BYTES;
        const uint32_t uB = uA + A_STAGE;

#pragma unroll
        for (int ks = 0; ks < 4; ks++) {
            uint32_t a[4][4], b[4][4];
            const uint32_t cA = ((uint32_t)(ks * 2) + colA_half) * 16;
            const uint32_t cB = ((uint32_t)(ks * 2) + colB_half) * 16;
#pragma unroll
            for (int mt = 0; mt < 4; mt++)
                LDSM4(a[mt][0], a[mt][1], a[mt][2], a[mt][3],
                      uA + rowoffA[mt] + (cA ^ xorv));
#pragma unroll
            for (int nt = 0; nt < 4; nt++)
                LDSM4(b[nt][0], b[nt][1], b[nt][2], b[nt][3],
                      uB + rowoffB[nt] + (cB ^ xorv));
#pragma unroll
            for (int mt = 0; mt < 4; mt++)
#pragma unroll
                for (int nt = 0; nt < 4; nt++) {
                    MMA16816(acc[mt][2 * nt],     a[mt], b[nt][0], b[nt][1]);
                    MMA16816(acc[mt][2 * nt + 1], a[mt], b[nt][2], b[nt][3]);
                }
        }

        if (lane == 0) MBAR_ARRIVE(mb_empty[st]);

        if (tid == 0 && L + STAGES < totL) {
            MBAR_WAIT(mb_empty[st], ph);
            fill_chunk(usmem, mb_full[st], bx, L + STAGES);
        }

        if ((L & 63) == 63) {
            const int t = bx + (L >> 6) * NSM;
            const int m0 = (t >> 4) * BM;
            const int n0 = (t & 15) * BN;
#pragma unroll
            for (int mt = 0; mt < 4; mt++) {
                const int row = m0 + wm * 64 + mt * 16 + (lane >> 2);
#pragma unroll
                for (int nt = 0; nt < 8; nt++) {
                    const int col = n0 + wn * 64 + nt * 8 + (lane & 3) * 2;
                    const float s0 = acc[mt][nt][0], s1 = acc[mt][nt][1];
                    const float s2 = acc[mt][nt][2], s3 = acc[mt][nt][3];
                    *reinterpret_cast<float2*>(Out + (size_t)row * N_TOT + col) =
                        make_float2((s0 >= 1.0f) ? 1.0f : 0.0f, (s1 >= 1.0f) ? 1.0f : 0.0f);
                    *reinterpret_cast<float2*>(Out + (size_t)(row + 8) * N_TOT + col) =
                        make_float2((s2 >= 1.0f) ? 1.0f : 0.0f, (s3 >= 1.0f) ? 1.0f : 0.0f);
                    if (s0 > MARG_LO && s0 < MARG_HI) {
                        unsigned int i = atomicAdd(&g_cnt, 1u);
                        if (i < LIST_CAP) { g_mn[i] = ((unsigned)row << 12) | (unsigned)col; g_hs[i] = s0; }
                    }
                    if (s1 > MARG_LO && s1 < MARG_HI) {
                        unsigned int i = atomicAdd(&g_cnt, 1u);
                        if (i < LIST_CAP) { g_mn[i] = ((unsigned)row << 12) | (unsigned)(col + 1); g_hs[i] = s1; }
                    }
                    if (s2 > MARG_LO && s2 < MARG_HI) {
                        unsigned int i = atomicAdd(&g_cnt, 1u);
                        if (i < LIST_CAP) { g_mn[i] = ((unsigned)(row + 8) << 12) | (unsigned)col; g_hs[i] = s2; }
                    }
                    if (s3 > MARG_LO && s3 < MARG_HI) {
                        unsigned int i = atomicAdd(&g_cnt, 1u);
                        if (i < LIST_CAP) { g_mn[i] = ((unsigned)(row + 8) << 12) | (unsigned)(col + 1); g_hs[i] = s3; }
                    }
#pragma unroll
                    for (int e = 0; e < 4; e++) acc[mt][nt][e] = 0.0f;
                }
            }
        }
    }
}

// ---------------- fixup ----------------
__global__ __launch_bounds__(256)
void fixup(float* __restrict__ Out) {
    const int lane = threadIdx.x & 31;
    const int gw = blockIdx.x * (blockDim.x >> 5) + (threadIdx.x >> 5);
    const int nwarps = gridDim.x * (blockDim.x >> 5);
    const unsigned int cnt = min(g_cnt, LIST_CAP);

    for (unsigned int i = gw; i < cnt; i += nwarps) {
        const unsigned int mn = g_mn[i];
        const float hs = g_hs[i];
        const int m = mn >> 12, n = mn & 4095;

        const uint4* lp = reinterpret_cast<const uint4*>(g_lo16 + (size_t)m * K_SRC) + lane * 16;
        const uint4* wp = reinterpret_cast<const uint4*>(g_w8  + (size_t)n * K_SRC) + lane * 8;

        int s = 0;
#pragma unroll
        for (int q = 0; q < 8; q++) {
            uint4 wv = wp[q];
            uint4 l0 = lp[2 * q], l1 = lp[2 * q + 1];
            s = __dp2a_lo((int)l0.x, (int)wv.x, s);
            s = __dp2a_hi((int)l0.y, (int)wv.x, s);
            s = __dp2a_lo((int)l0.z, (int)wv.y, s);
            s = __dp2a_hi((int)l0.w, (int)wv.y, s);
            s = __dp2a_lo((int)l1.x, (int)wv.z, s);
            s = __dp2a_hi((int)l1.y, (int)wv.z, s);
            s = __dp2a_lo((int)l1.z, (int)wv.w, s);
            s = __dp2a_hi((int)l1.w, (int)wv.w, s);
        }
#pragma unroll
        for (int off = 16; off; off >>= 1)
            s += __shfl_xor_sync(0xFFFFFFFFu, s, off);

        if (lane == 0) {
            const float tot = hs + (float)s * 7.4505805969238281e-9f;   // 2^-27
            Out[(size_t)m * N_TOT + n] = (tot >= 1.0f) ? 1.0f : 0.0f;
        }
    }
}

// ---------------- host ----------------
extern "C" void kernel_launch(void* const* d_in, const int* in_sizes, int n_in,
                              void* d_out, int out_size) {
    const float* X = (const float*)d_in[0];   // [8192, 4096]
    const float* S = (const float*)d_in[1];   // [4096, 4096]
    float* Out = (float*)d_out;

    cudaFuncSetAttribute(gemm_hi, cudaFuncAttributeMaxDynamicSharedMemorySize, SMEM_TOTAL);

    conv_all<<<dim3(80, 64), 256>>>(X, S);
    gemm_hi<<<NSM, 256, SMEM_TOTAL>>>(Out);
    fixup<<<2048, 256>>>(Out);
}